// round 15
// baseline (speedup 1.0000x reference)
#include <cuda_runtime.h>
#include <cuda_bf16.h>
#include <math.h>
#include <stdint.h>

// SpatialAttention, round 13: warp-specialized, FAT warp tiles (4+4 warps).
// Warps 0-3: stage K, QK (3-term bf16 hi/lo m16n8k16, 32s x 64t each), exp, P.
// Warps 4-7: stage V, PV (tf32 m16n8k8, 64e x 64t each, 128 accums), epilogue.
// Halves redundant fragment LDS vs 8+8 config; 256 threads, ~255 regs available.
// TQ=128, TK=64, grid 32x4 = 128 CTAs (one wave).

#define D        128
#define S_TOTAL  4096
#define TQ       128
#define TK       64
#define NT       256
#define SKP      69      // word stride, packed bf16x2 K/Q [row][c/2 + pad]
#define SQ       136     // float stride for Ps buffers [s][t + pad]
#define SV       76      // float stride for Vt [e][s + pad]
#define NBATCH   4

#define BAR_SYNC(id, cnt)   asm volatile("bar.sync %0, %1;"   :: "r"(id), "r"(cnt) : "memory")
#define BAR_ARRIVE(id, cnt) asm volatile("bar.arrive %0, %1;" :: "r"(id), "r"(cnt) : "memory")

__device__ __forceinline__ float tf32_rna(float x) {
    uint32_t u;
    asm("cvt.rna.tf32.f32 %0, %1;" : "=r"(u) : "f"(x));
    return __uint_as_float(u);
}
__device__ __forceinline__ void mma_tf32(float c[4], const uint32_t a[4], const uint32_t b[2]) {
    asm volatile(
        "mma.sync.aligned.m16n8k8.row.col.f32.tf32.tf32.f32 "
        "{%0,%1,%2,%3}, {%4,%5,%6,%7}, {%8,%9}, {%0,%1,%2,%3};\n"
        : "+f"(c[0]), "+f"(c[1]), "+f"(c[2]), "+f"(c[3])
        : "r"(a[0]), "r"(a[1]), "r"(a[2]), "r"(a[3]), "r"(b[0]), "r"(b[1]));
}
__device__ __forceinline__ void mma_bf16(float c[4], const uint32_t a[4], const uint32_t b[2]) {
    asm volatile(
        "mma.sync.aligned.m16n8k16.row.col.f32.bf16.bf16.f32 "
        "{%0,%1,%2,%3}, {%4,%5,%6,%7}, {%8,%9}, {%0,%1,%2,%3};\n"
        : "+f"(c[0]), "+f"(c[1]), "+f"(c[2]), "+f"(c[3])
        : "r"(a[0]), "r"(a[1]), "r"(a[2]), "r"(a[3]), "r"(b[0]), "r"(b[1]));
}
__device__ __forceinline__ uint32_t pack_bf16(__nv_bfloat16 lo, __nv_bfloat16 hi) {
    return (uint32_t)*(const uint16_t*)&lo | ((uint32_t)*(const uint16_t*)&hi << 16);
}

__global__ __launch_bounds__(NT, 1)
void spatial_attn_ws2(const float* __restrict__ key,
                      const float* __restrict__ query,
                      const float* __restrict__ value,
                      float* __restrict__ out)
{
    extern __shared__ float smf[];
    uint32_t* QHI = (uint32_t*)smf;           // [TQ][SKP]
    uint32_t* QLO = QHI + TQ * SKP;
    uint32_t* KHI = QLO + TQ * SKP;           // [TK][SKP]
    uint32_t* KLO = KHI + TK * SKP;
    float*    Vt  = (float*)(KLO + TK * SKP); // [D][SV]
    float*    Ps  = Vt + D * SV;              // [2][TK][SQ] double buffer
    float*    l_s = Ps + 2 * TK * SQ;         // [TQ]

    const int tid = threadIdx.x;
    const int b   = blockIdx.y;
    const int tq0 = blockIdx.x * TQ;

    const float* qb = query + (size_t)b * D * S_TOTAL;
    const float* kb = key   + (size_t)b * D * S_TOTAL;
    const float* vb = value + (size_t)b * D * S_TOTAL;
    float*       ob = out   + (size_t)b * D * S_TOTAL;

    const float qk_scale = 0.08838834764831845f;  // 1/sqrt(128)

    // ---- stage Q once (all 256 threads): scale, bf16 hi/lo, packed [t][c/2] ----
    #pragma unroll 4
    for (int it = 0; it < 16; ++it) {
        int f   = it * NT + tid;
        int c   = f >> 5;
        int t4  = (f & 31) << 2;
        float4 q4 = *(const float4*)(qb + (size_t)c * S_TOTAL + tq0 + t4);
        float qv[4] = {q4.x * qk_scale, q4.y * qk_scale, q4.z * qk_scale, q4.w * qk_scale};
        #pragma unroll
        for (int j = 0; j < 4; ++j) {
            __nv_bfloat16 h = __float2bfloat16(qv[j]);
            __nv_bfloat16 l = __float2bfloat16(qv[j] - __bfloat162float(h));
            int half = ((t4 + j) * SKP + (c >> 1)) * 2 + (c & 1);
            ((__nv_bfloat16*)QHI)[half] = h;
            ((__nv_bfloat16*)QLO)[half] = l;
        }
    }
    if (tid < TQ) l_s[tid] = 0.f;
    __syncthreads();

    const int lane = tid & 31;
    const int wid  = tid >> 5;
    const int g    = lane >> 2;
    const int tg   = lane & 3;

    if (wid < 4) {
        // ================= QK producer group (warps 0-3) =================
        // S tile [TK=64] x [TQ=128]; warp grid 2m x 2n, each 32s x 64t
        const int qk_m0 = (wid >> 1) * 32;
        const int qk_n0 = (wid & 1) * 64;
        float lreg[8][2];
        #pragma unroll
        for (int ni = 0; ni < 8; ++ni) { lreg[ni][0] = 0.f; lreg[ni][1] = 0.f; }

        for (int i = 0; i < S_TOTAL / TK; ++i) {
            const int s0 = i * TK;
            // --- stage K: coalesced scalar LDG, conflict-free packed STS.32 ---
            BAR_SYNC(2, 128);                 // QK warps done reading K(i-1)
            #pragma unroll 4
            for (int it = 0; it < 32; ++it) {
                int u  = it * 128 + tid;
                int s  = u & 63;
                int cp = u >> 6;              // channel pair 0..63
                float k0v = kb[(size_t)(2 * cp)     * S_TOTAL + s0 + s];
                float k1v = kb[(size_t)(2 * cp + 1) * S_TOTAL + s0 + s];
                __nv_bfloat16 h0 = __float2bfloat16(k0v);
                __nv_bfloat16 l0 = __float2bfloat16(k0v - __bfloat162float(h0));
                __nv_bfloat16 h1 = __float2bfloat16(k1v);
                __nv_bfloat16 l1 = __float2bfloat16(k1v - __bfloat162float(h1));
                KHI[s * SKP + cp] = pack_bf16(h0, h1);
                KLO[s * SKP + cp] = pack_bf16(l0, l1);
            }
            BAR_SYNC(2, 128);                 // K(i) ready

            // --- QK: 3-term bf16 (hh + hl + lh), 32x64 per warp ---
            float c[2][8][4];
            #pragma unroll
            for (int mi = 0; mi < 2; ++mi)
                #pragma unroll
                for (int ni = 0; ni < 8; ++ni)
                    #pragma unroll
                    for (int r = 0; r < 4; ++r) c[mi][ni][r] = 0.f;

            #pragma unroll
            for (int kbk = 0; kbk < 8; ++kbk) {
                int k0w = kbk * 8;
                uint32_t ahi[2][4], alo[2][4], bhi[8][2], blo[8][2];
                #pragma unroll
                for (int mi = 0; mi < 2; ++mi) {
                    int m = qk_m0 + mi * 16 + g;
                    ahi[mi][0] = KHI[m * SKP + k0w + tg];
                    ahi[mi][1] = KHI[(m + 8) * SKP + k0w + tg];
                    ahi[mi][2] = KHI[m * SKP + k0w + tg + 4];
                    ahi[mi][3] = KHI[(m + 8) * SKP + k0w + tg + 4];
                    alo[mi][0] = KLO[m * SKP + k0w + tg];
                    alo[mi][1] = KLO[(m + 8) * SKP + k0w + tg];
                    alo[mi][2] = KLO[m * SKP + k0w + tg + 4];
                    alo[mi][3] = KLO[(m + 8) * SKP + k0w + tg + 4];
                }
                #pragma unroll
                for (int ni = 0; ni < 8; ++ni) {
                    int n = qk_n0 + ni * 8 + g;
                    bhi[ni][0] = QHI[n * SKP + k0w + tg];
                    bhi[ni][1] = QHI[n * SKP + k0w + tg + 4];
                    blo[ni][0] = QLO[n * SKP + k0w + tg];
                    blo[ni][1] = QLO[n * SKP + k0w + tg + 4];
                }
                #pragma unroll
                for (int mi = 0; mi < 2; ++mi)
                    #pragma unroll
                    for (int ni = 0; ni < 8; ++ni) {
                        mma_bf16(c[mi][ni], ahi[mi], bhi[ni]);
                        mma_bf16(c[mi][ni], ahi[mi], blo[ni]);
                        mma_bf16(c[mi][ni], alo[mi], bhi[ni]);
                    }
            }

            // --- exp in regs, accumulate l ---
            #pragma unroll
            for (int mi = 0; mi < 2; ++mi)
                #pragma unroll
                for (int ni = 0; ni < 8; ++ni) {
                    c[mi][ni][0] = __expf(c[mi][ni][0]);
                    c[mi][ni][1] = __expf(c[mi][ni][1]);
                    c[mi][ni][2] = __expf(c[mi][ni][2]);
                    c[mi][ni][3] = __expf(c[mi][ni][3]);
                    lreg[ni][0] += c[mi][ni][0] + c[mi][ni][2];
                    lreg[ni][1] += c[mi][ni][1] + c[mi][ni][3];
                }

            // --- wait P buffer empty, store P (tf32-rounded), signal full ---
            if (i >= 2) BAR_SYNC(6 + (i & 1), 256);
            float* Pb = Ps + (i & 1) * TK * SQ;
            #pragma unroll
            for (int mi = 0; mi < 2; ++mi)
                #pragma unroll
                for (int ni = 0; ni < 8; ++ni) {
                    int r  = qk_m0 + mi * 16 + g;
                    int cc = qk_n0 + ni * 8 + 2 * tg;
                    *(float2*)(Pb + r * SQ + cc) =
                        make_float2(tf32_rna(c[mi][ni][0]), tf32_rna(c[mi][ni][1]));
                    *(float2*)(Pb + (r + 8) * SQ + cc) =
                        make_float2(tf32_rna(c[mi][ni][2]), tf32_rna(c[mi][ni][3]));
                }
            BAR_ARRIVE(4 + (i & 1), 256);
        }

        // --- denominator: reduce over g-lanes, combine two m-warps via atomics ---
        #pragma unroll
        for (int ni = 0; ni < 8; ++ni)
            #pragma unroll
            for (int h = 0; h < 2; ++h) {
                float v = lreg[ni][h];
                v += __shfl_xor_sync(0xffffffffu, v, 4);
                v += __shfl_xor_sync(0xffffffffu, v, 8);
                v += __shfl_xor_sync(0xffffffffu, v, 16);
                if (g == 0) atomicAdd(&l_s[qk_n0 + ni * 8 + 2 * tg + h], v);
            }
        BAR_ARRIVE(1, 256);
    } else {
        // ================= PV consumer group (warps 4-7) =================
        // O tile [128 e] x [128 t]; warp grid 2m x 2n, each 64e x 64t
        const int pw    = wid - 4;
        const int ptid  = tid - 128;
        const int pv_m0 = (pw >> 1) * 64;
        const int pv_n0 = (pw & 1) * 64;

        float o[4][8][4];
        #pragma unroll
        for (int mi = 0; mi < 4; ++mi)
            #pragma unroll
            for (int ni = 0; ni < 8; ++ni)
                #pragma unroll
                for (int r = 0; r < 4; ++r) o[mi][ni][r] = 0.f;

        for (int i = 0; i < S_TOTAL / TK; ++i) {
            const int s0 = i * TK;
            // --- stage V (tf32-rounded, [e][s]) ---
            BAR_SYNC(3, 128);                 // PV warps done reading V(i-1)
            #pragma unroll 4
            for (int it = 0; it < 16; ++it) {
                int f  = it * 128 + ptid;
                int e  = f >> 4;
                int s4 = (f & 15) << 2;
                float4 v4 = *(const float4*)(vb + (size_t)e * S_TOTAL + s0 + s4);
                *(float4*)(Vt + e * SV + s4) =
                    make_float4(tf32_rna(v4.x), tf32_rna(v4.y), tf32_rna(v4.z), tf32_rna(v4.w));
            }
            BAR_SYNC(3, 128);                 // V(i) ready

            BAR_SYNC(4 + (i & 1), 256);       // wait P buffer full
            const float* Pb = Ps + (i & 1) * TK * SQ;

            #pragma unroll
            for (int kbk = 0; kbk < 8; ++kbk) {
                int k0 = kbk * 8;
                uint32_t a[4][4], bb[8][2];
                #pragma unroll
                for (int mi = 0; mi < 4; ++mi) {
                    int m = pv_m0 + mi * 16 + g;
                    a[mi][0] = __float_as_uint(Vt[m * SV + k0 + tg]);
                    a[mi][1] = __float_as_uint(Vt[(m + 8) * SV + k0 + tg]);
                    a[mi][2] = __float_as_uint(Vt[m * SV + k0 + tg + 4]);
                    a[mi][3] = __float_as_uint(Vt[(m + 8) * SV + k0 + tg + 4]);
                }
                #pragma unroll
                for (int ni = 0; ni < 8; ++ni) {
                    int n = pv_n0 + ni * 8 + g;
                    bb[ni][0] = __float_as_uint(Pb[(k0 + tg) * SQ + n]);
                    bb[ni][1] = __float_as_uint(Pb[(k0 + tg + 4) * SQ + n]);
                }
                #pragma unroll
                for (int mi = 0; mi < 4; ++mi)
                    #pragma unroll
                    for (int ni = 0; ni < 8; ++ni)
                        mma_tf32(o[mi][ni], a[mi], bb[ni]);
            }
            BAR_ARRIVE(6 + (i & 1), 256);     // P buffer empty
        }

        BAR_SYNC(1, 256);                     // l_s final
        // --- epilogue: divide by l, store ---
        #pragma unroll
        for (int mi = 0; mi < 4; ++mi)
            #pragma unroll
            for (int ni = 0; ni < 8; ++ni) {
                int e  = pv_m0 + mi * 16 + g;
                int cc = pv_n0 + ni * 8 + 2 * tg;
                float2 l2 = *(const float2*)(l_s + cc);
                float r0 = 1.f / l2.x, r1 = 1.f / l2.y;
                *(float2*)(ob + (size_t)e * S_TOTAL + tq0 + cc) =
                    make_float2(o[mi][ni][0] * r0, o[mi][ni][1] * r1);
                *(float2*)(ob + (size_t)(e + 8) * S_TOTAL + tq0 + cc) =
                    make_float2(o[mi][ni][2] * r0, o[mi][ni][3] * r1);
            }
    }
}

extern "C" void kernel_launch(void* const* d_in, const int* in_sizes, int n_in,
                              void* d_out, int out_size)
{
    const float* key   = (const float*)d_in[0];
    const float* query = (const float*)d_in[1];
    const float* value = (const float*)d_in[2];
    float* out = (float*)d_out;

    int smem_bytes = (2 * TQ * SKP + 2 * TK * SKP) * 4
                   + (D * SV + 2 * TK * SQ + TQ) * (int)sizeof(float);   // ~210 KB
    cudaFuncSetAttribute(spatial_attn_ws2,
                         cudaFuncAttributeMaxDynamicSharedMemorySize, smem_bytes);

    dim3 grid(S_TOTAL / TQ, NBATCH);
    spatial_attn_ws2<<<grid, NT, smem_bytes>>>(key, query, value, out);
}